// round 5
// baseline (speedup 1.0000x reference)
#include <cuda_runtime.h>
#include <cuda_bf16.h>

// Problem dims
#define BATCH 256
#define HID   512
#define SEQ   250
#define INDIM 5

// Step-kernel tiling: 128 CTAs = 2 batch groups (M=128) x 64 hidden slices (HC=8 -> N=32 gate cols)
#define GRID_STEP    128
#define THREADS_STEP 128
#define HC 8
#define NC 32          // 4 gates * HC

// SMEM pitches (elements) chosen for conflict-free fragment loads
#define APITCH 520     // bf16 elements per A row (512 + 8)
#define BPITCH 516     // f32 elements per B row (512 + 4)

#define SA_BYTES (128 * APITCH * 2)            // 133120
#define SB_BYTES (NC * BPITCH * 4)             // 66048
#define SX_BYTES (128 * INDIM * 4)             // 2560
#define SWIH_BYTES (NC * INDIM * 4)            // 640
#define SBIAS_BYTES (NC * 4)                   // 128
#define SMEM_BYTES (SA_BYTES + SB_BYTES + SX_BYTES + SWIH_BYTES + SBIAS_BYTES) // 202496

// Persistent state (device globals: no allocation in kernel_launch)
__device__ __nv_bfloat16 g_h[2][BATCH * HID];
__device__ float         g_c[BATCH * HID];

__device__ __forceinline__ float sigmf_(float x) { return 1.0f / (1.0f + expf(-x)); }
__device__ __forceinline__ unsigned f2u(float f) { return __float_as_uint(f); }

// Round fp32 -> tf32 (round-to-nearest) keeping the 32-bit container
__device__ __forceinline__ float cvt_tf32(float f) {
    unsigned r;
    asm("cvt.rna.tf32.f32 %0, %1;" : "=r"(r) : "f"(f));
    return __uint_as_float(r);
}

__device__ __forceinline__ void mma_tf32(float* c, const unsigned* a, unsigned b0, unsigned b1) {
    asm volatile(
        "mma.sync.aligned.m16n8k8.row.col.f32.tf32.tf32.f32 "
        "{%0,%1,%2,%3}, {%4,%5,%6,%7}, {%8,%9}, {%0,%1,%2,%3};"
        : "+f"(c[0]), "+f"(c[1]), "+f"(c[2]), "+f"(c[3])
        : "r"(a[0]), "r"(a[1]), "r"(a[2]), "r"(a[3]), "r"(b0), "r"(b1));
}

__global__ void zero_state_kernel() {
    int i = blockIdx.x * blockDim.x + threadIdx.x;
    if (i < BATCH * HID) {
        g_c[i] = 0.0f;
        g_h[0][i] = __float2bfloat16(0.0f);
    }
}

// One LSTM timestep: gates = (b_ih + b_hh) + x_t @ W_ih^T + h @ W_hh^T, then state update.
// CTA (p, q): batch rows [p*128, p*128+128), hidden units [q*8, q*8+8) (all 4 gates).
__global__ __launch_bounds__(THREADS_STEP)
void lstm_step_kernel(const float* __restrict__ strokes,
                      const float* __restrict__ W_ih,
                      const float* __restrict__ W_hh,
                      const float* __restrict__ b_ih,
                      const float* __restrict__ b_hh,
                      int t, int hsel) {
    extern __shared__ char smem[];
    __nv_bfloat16* sA   = (__nv_bfloat16*)smem;                         // [128][APITCH] bf16 h tile
    float*         sB   = (float*)(smem + SA_BYTES);                    // [32][BPITCH]  tf32 W rows
    float*         sx   = (float*)(smem + SA_BYTES + SB_BYTES);         // [128][5]      x_t tile
    float*         swih = sx + 128 * INDIM;                             // [32][5]
    float*         sbias = swih + NC * INDIM;                           // [32]

    const int tid = threadIdx.x;
    const int q = blockIdx.x & 63;
    const int p = blockIdx.x >> 6;
    const int rowBase = p * 128;
    const int jBase = q * HC;

    const __nv_bfloat16* __restrict__ hin = g_h[hsel] + rowBase * HID;  // contiguous 128 rows
    __nv_bfloat16* __restrict__ hout = g_h[hsel ^ 1];

    // ---- Load A: 128 x 512 bf16 (128 KB), vectorized 16B ----
    {
        const uint4* hin4 = (const uint4*)hin;  // 64 uint4 per row
        #pragma unroll
        for (int it = 0; it < 64; it++) {
            int idx = tid + it * 128;
            int r = idx >> 6, c = idx & 63;
            uint4 v = hin4[idx];
            *(uint4*)(sA + r * APITCH + c * 8) = v;
        }
    }
    // ---- Load B: 32 gate-rows of W_hh (each 512 f32), tf32-rounded ----
    #pragma unroll
    for (int it = 0; it < 32; it++) {
        int idx = tid + it * 128;
        int n = idx >> 7, c = idx & 127;               // 128 float4 per row
        int gate = n >> 3, j = n & 7;
        const float4* src = (const float4*)(W_hh + (size_t)(gate * HID + jBase + j) * HID);
        float4 v = src[c];
        v.x = cvt_tf32(v.x); v.y = cvt_tf32(v.y); v.z = cvt_tf32(v.z); v.w = cvt_tf32(v.w);
        *(float4*)(sB + n * BPITCH + c * 4) = v;
    }
    // ---- x_t tile, W_ih slice, fused biases ----
    for (int idx = tid; idx < 128 * INDIM; idx += THREADS_STEP) {
        int r = idx / INDIM, i = idx - r * INDIM;
        sx[idx] = strokes[(size_t)(rowBase + r) * (SEQ * INDIM) + t * INDIM + i];
    }
    if (tid < NC) {
        int gate = tid >> 3, j = tid & 7;
        int gr = gate * HID + jBase + j;
        sbias[tid] = b_ih[gr] + b_hh[gr];
        #pragma unroll
        for (int i = 0; i < INDIM; i++) swih[tid * INDIM + i] = W_ih[gr * INDIM + i];
    }
    __syncthreads();

    // ---- MMA mainloop: each warp M=32 (2 m-tiles), N=32 (4 n-tiles), K=512 ----
    const int warp = tid >> 5, lane = tid & 31;
    const int g4 = lane >> 2, tg = lane & 3;

    float acc[2][4][4];
    #pragma unroll
    for (int a = 0; a < 2; a++)
        #pragma unroll
        for (int b = 0; b < 4; b++)
            #pragma unroll
            for (int c = 0; c < 4; c++) acc[a][b][c] = 0.0f;

    const __nv_bfloat16* A0 = sA + (warp * 32 + g4) * APITCH;
    const float* Bb = sB + g4 * BPITCH;

    #pragma unroll 4
    for (int ks = 0; ks < 64; ks++) {
        const int k0 = ks * 8;
        unsigned a[2][4];
        #pragma unroll
        for (int mt = 0; mt < 2; mt++) {
            const __nv_bfloat16* r0 = A0 + mt * 16 * APITCH + k0;
            const __nv_bfloat16* r1 = r0 + 8 * APITCH;
            // bf16 -> f32 is exact and a valid tf32 operand (<=8 mantissa bits)
            a[mt][0] = f2u(__bfloat162float(r0[tg]));
            a[mt][1] = f2u(__bfloat162float(r1[tg]));
            a[mt][2] = f2u(__bfloat162float(r0[tg + 4]));
            a[mt][3] = f2u(__bfloat162float(r1[tg + 4]));
        }
        #pragma unroll
        for (int nt = 0; nt < 4; nt++) {
            const float* bp = Bb + nt * 8 * BPITCH + k0;
            unsigned b0 = f2u(bp[tg]);
            unsigned b1 = f2u(bp[tg + 4]);
            mma_tf32(acc[0][nt], a[0], b0, b1);
            mma_tf32(acc[1][nt], a[1], b0, b1);
        }
    }

    // ---- Epilogue: each thread owns all 4 gates for its (row, j) pairs -> local update ----
    // C frag (m16n8): elem0 (row g4, col 2tg), elem1 (g4, 2tg+1), elem2 (g4+8, 2tg), elem3 (g4+8, 2tg+1)
    #pragma unroll
    for (int mt = 0; mt < 2; mt++) {
        #pragma unroll
        for (int half = 0; half < 2; half++) {
            int rloc = warp * 32 + mt * 16 + g4 + half * 8;
            int grow = rowBase + rloc;
            #pragma unroll
            for (int bb = 0; bb < 2; bb++) {
                int e = half * 2 + bb;
                int j = tg * 2 + bb;
                float xs[4];
                #pragma unroll
                for (int gate = 0; gate < 4; gate++) {
                    int n = gate * 8 + j;
                    float s = sbias[n];
                    #pragma unroll
                    for (int i = 0; i < INDIM; i++) s += sx[rloc * INDIM + i] * swih[n * INDIM + i];
                    xs[gate] = s;
                }
                float iv = acc[mt][0][e] + xs[0];
                float fv = acc[mt][1][e] + xs[1];
                float gv = acc[mt][2][e] + xs[2];
                float ov = acc[mt][3][e] + xs[3];
                int cidx = grow * HID + jBase + j;
                float cn = sigmf_(fv) * g_c[cidx] + sigmf_(iv) * tanhf(gv);
                g_c[cidx] = cn;
                hout[cidx] = __float2bfloat16(sigmf_(ov) * tanhf(cn));
            }
        }
    }
}

// out[b] = sigmoid(leaky_relu(h_final . W_out + b_out, 0.1))
__global__ void head_kernel(const float* __restrict__ W_out,
                            const float* __restrict__ b_out,
                            float* __restrict__ out) {
    int b = blockIdx.x;
    int lane = threadIdx.x;
    float s = 0.0f;
    #pragma unroll
    for (int j = lane; j < HID; j += 32)
        s += __bfloat162float(g_h[0][b * HID + j]) * W_out[j];  // SEQ even -> final h in buffer 0
    #pragma unroll
    for (int o = 16; o; o >>= 1) s += __shfl_xor_sync(0xffffffffu, s, o);
    if (lane == 0) {
        float raw = s + b_out[0];
        float lr = raw > 0.0f ? raw : 0.1f * raw;
        out[b] = 1.0f / (1.0f + expf(-lr));
    }
}

extern "C" void kernel_launch(void* const* d_in, const int* in_sizes, int n_in,
                              void* d_out, int out_size) {
    const float* strokes = (const float*)d_in[0];
    const float* W_ih    = (const float*)d_in[1];
    const float* W_hh    = (const float*)d_in[2];
    const float* b_ih    = (const float*)d_in[3];
    const float* b_hh    = (const float*)d_in[4];
    const float* W_out   = (const float*)d_in[5];
    const float* b_out   = (const float*)d_in[6];
    float* out = (float*)d_out;

    cudaFuncSetAttribute(lstm_step_kernel,
                         cudaFuncAttributeMaxDynamicSharedMemorySize, SMEM_BYTES);

    zero_state_kernel<<<(BATCH * HID + 255) / 256, 256>>>();
    for (int t = 0; t < SEQ; t++) {
        lstm_step_kernel<<<GRID_STEP, THREADS_STEP, SMEM_BYTES>>>(
            strokes, W_ih, W_hh, b_ih, b_hh, t, t & 1);
    }
    head_kernel<<<BATCH, 32>>>(W_out, b_out, out);
}